// round 10
// baseline (speedup 1.0000x reference)
#include <cuda_runtime.h>
#include <cuda_bf16.h>

#define NBLOCKS 2048

// Scratch (no device allocs allowed).
__device__ double   g_part[NBLOCKS];
__device__ unsigned g_ticket;   // zero-init; reset to 0 by the closing block each call

// x: [rows, 128] fp32. One warp per row, 4 rows per iteration, grid-stride.
// min-blocks=3 -> 85-register budget so ptxas keeps all 4 float4 loads live
// (front-batched MLP). regs=32 variants (R5/R9) serialized the loads.
__global__ void __launch_bounds__(256, 3) mrl_fused_kernel(
    const float* __restrict__ x,
    const void* __restrict__ target,
    int rows, double inv_cnt,
    float* __restrict__ out)
{
    const int tid    = threadIdx.x;
    const int lane   = tid & 31;
    const int wid    = tid >> 5;
    const int gwarp  = (blockIdx.x * blockDim.x + tid) >> 5;
    const int nwarps = (gridDim.x * blockDim.x) >> 5;

    // ---- dtype probe (warp 0): int64 targets in [0,128) have all-zero odd words ----
    __shared__ int s_is64;
    const int* t32p = (const int*)target;
    if (wid == 0) {
        int nz = 0;
        #pragma unroll
        for (int j = 0; j < 4; j++)
            nz |= __ldg(t32p + 1 + 2 * (lane * 4 + j));
        unsigned any = __ballot_sync(0xFFFFFFFFu, nz != 0);
        if (lane == 0) s_is64 = (any == 0u) ? 1 : 0;
    }
    __syncthreads();
    const int is64 = s_is64;

    const int*       t32 = (const int*)target;
    const long long* t64 = (const long long*)target;

    float a0 = 0.f, a1 = 0.f, a2 = 0.f, a3 = 0.f;

    int r = gwarp * 4;
    const int stride = nwarps * 4;

    // Main path: 4 full rows per iteration (proven R4 dataflow).
    for (; r + 3 < rows; r += stride) {
        int t0, t1, t2, t3;
        if (is64) {
            const longlong2 ta = *reinterpret_cast<const longlong2*>(t64 + r);
            const longlong2 tb = *reinterpret_cast<const longlong2*>(t64 + r + 2);
            t0 = (int)ta.x; t1 = (int)ta.y; t2 = (int)tb.x; t3 = (int)tb.y;
        } else {
            const int4 t = *reinterpret_cast<const int4*>(t32 + r);
            t0 = t.x; t1 = t.y; t2 = t.z; t3 = t.w;
        }

        const float* p = x + (size_t)r * 128;
        // Front-batched: 4 x LDG.128 per lane (independent), then the
        // target-dependent broadcast pos loads (hit L2/L1, same row).
        const float4 v0 = reinterpret_cast<const float4*>(p        )[lane];
        const float4 v1 = reinterpret_cast<const float4*>(p + 128  )[lane];
        const float4 v2 = reinterpret_cast<const float4*>(p + 256  )[lane];
        const float4 v3 = reinterpret_cast<const float4*>(p + 384  )[lane];
        const float b0 = 0.5f - __ldg(p +       t0);
        const float b1 = 0.5f - __ldg(p + 128 + t1);
        const float b2 = 0.5f - __ldg(p + 256 + t2);
        const float b3 = 0.5f - __ldg(p + 384 + t3);

        a0 += fmaxf(v0.x + b0, 0.f) + fmaxf(v0.y + b0, 0.f)
            + fmaxf(v0.z + b0, 0.f) + fmaxf(v0.w + b0, 0.f);
        a1 += fmaxf(v1.x + b1, 0.f) + fmaxf(v1.y + b1, 0.f)
            + fmaxf(v1.z + b1, 0.f) + fmaxf(v1.w + b1, 0.f);
        a2 += fmaxf(v2.x + b2, 0.f) + fmaxf(v2.y + b2, 0.f)
            + fmaxf(v2.z + b2, 0.f) + fmaxf(v2.w + b2, 0.f);
        a3 += fmaxf(v3.x + b3, 0.f) + fmaxf(v3.y + b3, 0.f)
            + fmaxf(v3.z + b3, 0.f) + fmaxf(v3.w + b3, 0.f);
    }

    // Tail (none for the benchmark shape; kept for generality).
    for (; r < rows; r++) {
        const int tgt = is64 ? (int)t64[r] : t32[r];
        const float* p = x + (size_t)r * 128;
        const float4 v = reinterpret_cast<const float4*>(p)[lane];
        const float b  = 0.5f - __ldg(p + tgt);
        a0 += fmaxf(v.x + b, 0.f) + fmaxf(v.y + b, 0.f)
            + fmaxf(v.z + b, 0.f) + fmaxf(v.w + b, 0.f);
    }

    // Lane partials -> warp -> block.
    double d = (double)a0 + (double)a1 + (double)a2 + (double)a3;
    #pragma unroll
    for (int o = 16; o > 0; o >>= 1)
        d += __shfl_xor_sync(0xFFFFFFFFu, d, o);

    __shared__ double ws[8];
    if (lane == 0) ws[wid] = d;
    __syncthreads();

    __shared__ bool s_last;
    if (tid == 0) {
        double b = 0.0;
        #pragma unroll
        for (int i = 0; i < 8; i++) b += ws[i];
        g_part[blockIdx.x] = b;
        __threadfence();
        unsigned t = atomicAdd(&g_ticket, 1u);
        s_last = (t == (unsigned)gridDim.x - 1u);
    }
    __syncthreads();

    // ---- closing block: reduce all partials, finish, reset ticket ----
    if (s_last) {
        double s = 0.0;
        for (int i = tid; i < NBLOCKS; i += 256) s += g_part[i];
        #pragma unroll
        for (int o = 16; o > 0; o >>= 1)
            s += __shfl_xor_sync(0xFFFFFFFFu, s, o);
        if (lane == 0) ws[wid] = s;
        __syncthreads();
        if (tid == 0) {
            double b = 0.0;
            #pragma unroll
            for (int i = 0; i < 8; i++) b += ws[i];
            // Each row's target position contributed exactly max(0, 0.5) = 0.5.
            out[0] = (float)((b - 0.5 * (double)rows) * inv_cnt);
            g_ticket = 0;   // reset for the next (graph-replayed) call
        }
    }
}

extern "C" void kernel_launch(void* const* d_in, const int* in_sizes, int n_in,
                              void* d_out, int out_size)
{
    const float* x      = (const float*)d_in[0];   // [V, C, T] fp32
    const void*  target = d_in[1];                 // [V, C] int32 or int64 (auto-detected)
    float*       out    = (float*)d_out;

    const int T    = 128;
    const int rows = in_sizes[0] / T;              // V*C
    const double cnt = (double)rows * (double)(T - 1);

    mrl_fused_kernel<<<NBLOCKS, 256>>>(x, target, rows, 1.0 / cnt, out);
}

// round 11
// speedup vs baseline: 1.1586x; 1.1586x over previous
#include <cuda_runtime.h>
#include <cuda_bf16.h>

#define NBLOCKS 1024   // single wave: <= resident CTA capacity, perfectly even split

// Scratch (no device allocs allowed).
__device__ double   g_part[NBLOCKS];
__device__ unsigned g_ticket;   // zero-init; reset to 0 by the closing block each call

// x: [rows, 128] fp32. Each warp owns a CONTIGUOUS chunk of rows (DRAM page
// locality, warps naturally spread over address space), 4 rows per iteration.
__global__ void __launch_bounds__(256) mrl_fused_kernel(
    const float* __restrict__ x,
    const void* __restrict__ target,
    int rows, double inv_cnt,
    float* __restrict__ out)
{
    const int tid    = threadIdx.x;
    const int lane   = tid & 31;
    const int wid    = tid >> 5;
    const int gwarp  = (blockIdx.x * blockDim.x + tid) >> 5;
    const int nwarps = (gridDim.x * blockDim.x) >> 5;

    // ---- dtype probe (warp 0): int64 targets in [0,128) have all-zero odd words ----
    __shared__ int s_is64;
    const int* t32p = (const int*)target;
    if (wid == 0) {
        int nz = 0;
        #pragma unroll
        for (int j = 0; j < 4; j++)
            nz |= __ldg(t32p + 1 + 2 * (lane * 4 + j));
        unsigned any = __ballot_sync(0xFFFFFFFFu, nz != 0);
        if (lane == 0) s_is64 = (any == 0u) ? 1 : 0;
    }
    __syncthreads();
    const int is64 = s_is64;

    const int*       t32 = (const int*)target;
    const long long* t64 = (const long long*)target;

    // Contiguous chunk for this warp: [r0, r1)
    const int rpw = (rows + nwarps - 1) / nwarps;   // 64 for the bench shape
    int r        = gwarp * rpw;
    const int r1 = (r + rpw < rows) ? (r + rpw) : rows;

    float a0 = 0.f, a1 = 0.f, a2 = 0.f, a3 = 0.f;

    const float* p = x + (size_t)r * 128;

    // Main path: 4 sequential rows per iteration (R4-proven dataflow).
    for (; r + 3 < r1; r += 4, p += 512) {
        int t0, t1, t2, t3;
        if (is64) {
            const longlong2 ta = *reinterpret_cast<const longlong2*>(t64 + r);
            const longlong2 tb = *reinterpret_cast<const longlong2*>(t64 + r + 2);
            t0 = (int)ta.x; t1 = (int)ta.y; t2 = (int)tb.x; t3 = (int)tb.y;
        } else {
            const int4 t = *reinterpret_cast<const int4*>(t32 + r);
            t0 = t.x; t1 = t.y; t2 = t.z; t3 = t.w;
        }

        // Front-batched: 4 x LDG.128 (2 KB contiguous per warp) + 4 broadcast pos.
        const float4 v0 = reinterpret_cast<const float4*>(p        )[lane];
        const float4 v1 = reinterpret_cast<const float4*>(p + 128  )[lane];
        const float4 v2 = reinterpret_cast<const float4*>(p + 256  )[lane];
        const float4 v3 = reinterpret_cast<const float4*>(p + 384  )[lane];
        const float b0 = 0.5f - __ldg(p +       t0);
        const float b1 = 0.5f - __ldg(p + 128 + t1);
        const float b2 = 0.5f - __ldg(p + 256 + t2);
        const float b3 = 0.5f - __ldg(p + 384 + t3);

        a0 += fmaxf(v0.x + b0, 0.f) + fmaxf(v0.y + b0, 0.f)
            + fmaxf(v0.z + b0, 0.f) + fmaxf(v0.w + b0, 0.f);
        a1 += fmaxf(v1.x + b1, 0.f) + fmaxf(v1.y + b1, 0.f)
            + fmaxf(v1.z + b1, 0.f) + fmaxf(v1.w + b1, 0.f);
        a2 += fmaxf(v2.x + b2, 0.f) + fmaxf(v2.y + b2, 0.f)
            + fmaxf(v2.z + b2, 0.f) + fmaxf(v2.w + b2, 0.f);
        a3 += fmaxf(v3.x + b3, 0.f) + fmaxf(v3.y + b3, 0.f)
            + fmaxf(v3.z + b3, 0.f) + fmaxf(v3.w + b3, 0.f);
    }

    // Tail (none for the benchmark shape; kept for generality).
    for (; r < r1; r++, p += 128) {
        const int tgt = is64 ? (int)t64[r] : t32[r];
        const float4 v = reinterpret_cast<const float4*>(p)[lane];
        const float b  = 0.5f - __ldg(p + tgt);
        a0 += fmaxf(v.x + b, 0.f) + fmaxf(v.y + b, 0.f)
            + fmaxf(v.z + b, 0.f) + fmaxf(v.w + b, 0.f);
    }

    // Lane partials -> warp -> block.
    double d = (double)a0 + (double)a1 + (double)a2 + (double)a3;
    #pragma unroll
    for (int o = 16; o > 0; o >>= 1)
        d += __shfl_xor_sync(0xFFFFFFFFu, d, o);

    __shared__ double ws[8];
    if (lane == 0) ws[wid] = d;
    __syncthreads();

    __shared__ bool s_last;
    if (tid == 0) {
        double b = 0.0;
        #pragma unroll
        for (int i = 0; i < 8; i++) b += ws[i];
        g_part[blockIdx.x] = b;
        __threadfence();
        unsigned t = atomicAdd(&g_ticket, 1u);
        s_last = (t == (unsigned)gridDim.x - 1u);
    }
    __syncthreads();

    // ---- closing block: reduce all partials, finish, reset ticket ----
    if (s_last) {
        double s = 0.0;
        for (int i = tid; i < NBLOCKS; i += 256) s += g_part[i];
        #pragma unroll
        for (int o = 16; o > 0; o >>= 1)
            s += __shfl_xor_sync(0xFFFFFFFFu, s, o);
        if (lane == 0) ws[wid] = s;
        __syncthreads();
        if (tid == 0) {
            double b = 0.0;
            #pragma unroll
            for (int i = 0; i < 8; i++) b += ws[i];
            // Each row's target position contributed exactly max(0, 0.5) = 0.5.
            out[0] = (float)((b - 0.5 * (double)rows) * inv_cnt);
            g_ticket = 0;   // reset for the next (graph-replayed) call
        }
    }
}

extern "C" void kernel_launch(void* const* d_in, const int* in_sizes, int n_in,
                              void* d_out, int out_size)
{
    const float* x      = (const float*)d_in[0];   // [V, C, T] fp32
    const void*  target = d_in[1];                 // [V, C] int32 or int64 (auto-detected)
    float*       out    = (float*)d_out;

    const int T    = 128;
    const int rows = in_sizes[0] / T;              // V*C
    const double cnt = (double)rows * (double)(T - 1);

    mrl_fused_kernel<<<NBLOCKS, 256>>>(x, target, rows, 1.0 / cnt, out);
}